// round 16
// baseline (speedup 1.0000x reference)
#include <cuda_runtime.h>
#include <cstdint>

// SpectralConv2d via DHT — fused kernel; phases A and 2 on tensor cores
// (m16n8k8 tf32, 3xTF32). R16: phase-A operand swap — the constant cas table
// is the (pre-hi/lo-split) A-operand, x is the 2-register B-operand, halving
// the per-step convert chain. 3 independent accumulator chains retained.

#define NB 8
#define S  256

// ---------------------------------------------------------------------------
// Compile-time trig + tf32 fragment tables.
// ---------------------------------------------------------------------------
constexpr double CPI = 3.14159265358979323846264338327950288;

constexpr double tpoly_cos(double x) {
    double x2 = x * x, term = 1.0, sum = 1.0;
    for (int n = 1; n <= 12; n++) { term *= -x2 / ((2.0*n - 1) * (2.0*n)); sum += term; }
    return sum;
}
constexpr double tpoly_sin(double x) {
    double x2 = x * x, term = x, sum = x;
    for (int n = 1; n <= 12; n++) { term *= -x2 / ((2.0*n) * (2.0*n + 1)); sum += term; }
    return sum;
}
constexpr double cos256(int m) {
    m &= 255; int s = 1;
    if (m > 128) m = 256 - m;
    if (m > 64) { m = 128 - m; s = -1; }
    return s * tpoly_cos((CPI * m) / 128.0);
}
constexpr double sin256(int m) {
    m &= 255; int s = 1;
    if (m > 128) { m = 256 - m; s = -1; }
    if (m > 64) { m = 128 - m; }
    return s * tpoly_sin((CPI * m) / 128.0);
}
constexpr double casd(int m) { return cos256(m) + sin256(m); }

constexpr float tf_hi(double v) {
    float f = (float)v;
    unsigned u = __builtin_bit_cast(unsigned, f);
    u &= 0xFFFFE000u;
    return __builtin_bit_cast(float, u);
}
constexpr float tf_lo(double v) {
    float h = tf_hi(v);
    float l = (float)(v - (double)h);
    unsigned u = __builtin_bit_cast(unsigned, l);
    u &= 0xFFFFE000u;
    return __builtin_bit_cast(float, u);
}

struct alignas(16) F4 { float x, y, z, w; };

// Phase A (operand-swapped): D[y][i] = sum_k Bt[y][k] * X[k][i]
//   A-operand = Bt (16y x 8k tile): PAh/PAl[(ks*2+mt)*32+lane] =
//     {A[y0][k0], A[y1][k0], A[y0][k1], A[y1][k1]},
//     y0=16mt+g, y1=y0+8, k0=8ks+c, k1=k0+4   (g=lane>>2, c=lane&3)
// Phase 2: PM[(ks*32+nt)*32+lane], A-operand = R, B-operand = Mm (as in R15).
struct Tables {
    F4 PAh[32 * 2 * 32];
    F4 PAl[32 * 2 * 32];
    F4 PM[4 * 32 * 32];
};

constexpr Tables make_tables() {
    Tables t{};
    double cas[256] = {};
    for (int m = 0; m < 256; m++) cas[m] = casd(m);
    for (int ks = 0; ks < 32; ks++)
        for (int mt = 0; mt < 2; mt++)
            for (int lane = 0; lane < 32; lane++) {
                int c = lane & 3, g = lane >> 2;
                int y0 = 16 * mt + g, y1 = y0 + 8;
                int k0 = 8 * ks + c, k1 = k0 + 4;
                double a0 = cas[(k0 * y0) & 255], a1 = cas[(k0 * y1) & 255];
                double a2 = cas[(k1 * y0) & 255], a3 = cas[(k1 * y1) & 255];
                t.PAh[(ks * 2 + mt) * 32 + lane] = F4{tf_hi(a0), tf_hi(a1), tf_hi(a2), tf_hi(a3)};
                t.PAl[(ks * 2 + mt) * 32 + lane] = F4{tf_lo(a0), tf_lo(a1), tf_lo(a2), tf_lo(a3)};
            }
    for (int ks = 0; ks < 4; ks++)
        for (int nt = 0; nt < 32; nt++)
            for (int lane = 0; lane < 32; lane++) {
                int c = lane & 3, g = lane >> 2;
                int y0 = 8 * ks + c, y1 = y0 + 4, k = 8 * nt + g;
                double m0 = 0.0, m1 = 0.0;
                for (int j = 0; j < 32; j++) {
                    double cj = cas[(j * k) & 255];
                    m0 += cas[(8 * ((y0 * j) & 31)) & 255] * cj;
                    m1 += cas[(8 * ((y1 * j) & 31)) & 255] * cj;
                }
                m0 *= 0x1p-42; m1 *= 0x1p-42;
                t.PM[(ks * 32 + nt) * 32 + lane] =
                    F4{tf_hi(m0), tf_hi(m1), tf_lo(m0), tf_lo(m1)};
            }
    return t;
}

__device__ const Tables g_T = make_tables();

// ---------------------------------------------------------------------------
__device__ __forceinline__ uint32_t cvt_tf32(float f) {
    uint32_t r; asm("cvt.rna.tf32.f32 %0, %1;" : "=r"(r) : "f"(f)); return r;
}
#define MMA_TF32(d0,d1,d2,d3,a0,a1,a2,a3,b0,b1)                             \
    asm("mma.sync.aligned.m16n8k8.row.col.f32.tf32.tf32.f32 "               \
        "{%0,%1,%2,%3}, {%4,%5,%6,%7}, {%8,%9}, {%0,%1,%2,%3};"             \
        : "+f"(d0), "+f"(d1), "+f"(d2), "+f"(d3)                            \
        : "r"(a0), "r"(a1), "r"(a2), "r"(a3), "r"(b0), "r"(b1))

// ---------------------------------------------------------------------------
// F: fused DHT (mma) + channel mix (scalar) + trailing transforms (mma).
// One block per (b, blk, x); 256 threads = 8 warps.
// ---------------------------------------------------------------------------
__global__ __launch_bounds__(256) void f_fused(const float* __restrict__ xin,
                                               const float* __restrict__ w1,
                                               const float* __restrict__ w2,
                                               float* __restrict__ out) {
    __shared__ float xs[32 * 260];   // [i][k], pitch 260 (frag-LDS conflict-free)
    __shared__ float As[32 * 36];    // [i][y], pitch 36
    __shared__ float rst[32 * 36];   // [o][y], pitch 36

    int t    = threadIdx.x;
    int lane = t & 31, warp = t >> 5;
    int g    = lane >> 2, c = lane & 3;
    int bid  = blockIdx.x;
    int x    = bid & 31;
    int blk  = (bid >> 5) & 1;
    int b    = bid >> 6;
    int row  = blk ? (224 + x) : x;
    const float* w = blk ? w2 : w1;

    // ---- stage x rows into xs (coalesced) ----
    const float4* xb4 = (const float4*)(xin + (((size_t)b * 32) * S + row) * S);
#pragma unroll
    for (int n = t; n < 2048; n += 256) {
        int i = n >> 6, kc = n & 63;
        ((float4*)(xs + i * 260))[kc] = xb4[(size_t)i * (S * S / 4) + kc];
    }
    __syncthreads();

    // ---- phase A (swapped): D[y][i] = Bt(16y x 8k) @ X(8k x 8i) ----
    {
        int mt = warp & 1, nt = warp >> 1;   // mt: y-tile (2), nt: i-tile (4)
        const float* xq = xs + (8 * nt + g) * 260;   // row i = 8nt+g
        float hh0=0.f,hh1=0.f,hh2=0.f,hh3=0.f;   // Bt_hi * X_hi
        float lh0=0.f,lh1=0.f,lh2=0.f,lh3=0.f;   // Bt_lo * X_hi
        float hl0=0.f,hl1=0.f,hl2=0.f,hl3=0.f;   // Bt_hi * X_lo
        const float4* PH = (const float4*)g_T.PAh + mt * 32 + lane;
        const float4* PL = (const float4*)g_T.PAl + mt * 32 + lane;
#pragma unroll 8
        for (int ks = 0; ks < 32; ks++) {
            float f0 = xq[8 * ks + c];               // X[k=8ks+c][i]
            float f1 = xq[8 * ks + c + 4];           // X[k=8ks+c+4][i]
            uint32_t b0h = cvt_tf32(f0), b1h = cvt_tf32(f1);
            uint32_t b0l = __float_as_uint(f0 - __uint_as_float(b0h));
            uint32_t b1l = __float_as_uint(f1 - __uint_as_float(b1h));
            float4 ah = __ldg(PH + ks * 64);
            float4 al = __ldg(PL + ks * 64);
            uint32_t ah0 = __float_as_uint(ah.x), ah1 = __float_as_uint(ah.y);
            uint32_t ah2 = __float_as_uint(ah.z), ah3 = __float_as_uint(ah.w);
            uint32_t al0 = __float_as_uint(al.x), al1 = __float_as_uint(al.y);
            uint32_t al2 = __float_as_uint(al.z), al3 = __float_as_uint(al.w);
            MMA_TF32(hh0, hh1, hh2, hh3, ah0, ah1, ah2, ah3, b0h, b1h);
            MMA_TF32(lh0, lh1, lh2, lh3, al0, al1, al2, al3, b0h, b1h);
            MMA_TF32(hl0, hl1, hl2, hl3, ah0, ah1, ah2, ah3, b0l, b1l);
        }
        float d0 = (hh0 + lh0) + hl0;    // D[y=16mt+g  ][i=8nt+2c  ]
        float d1 = (hh1 + lh1) + hl1;    // D[y=16mt+g  ][i=8nt+2c+1]
        float d2 = (hh2 + lh2) + hl2;    // D[y=16mt+g+8][i=8nt+2c  ]
        float d3 = (hh3 + lh3) + hl3;    // D[y=16mt+g+8][i=8nt+2c+1]
        int i0 = 8 * nt + 2 * c, y0 = 16 * mt + g;
        As[i0 * 36 + y0]           = d0;
        As[(i0 + 1) * 36 + y0]     = d1;
        As[i0 * 36 + y0 + 8]       = d2;
        As[(i0 + 1) * 36 + y0 + 8] = d3;
    }

    // ---- zero-fill dead rows [32,224): stores drain during barrier ----
    {
        int img = bid >> 1, half = bid & 1;
        float4* o4 = (float4*)out + (size_t)img * 16384 + 2048 + half * 6144 + t;
#pragma unroll
        for (int j = 0; j < 24; j++) o4[j * 256] = make_float4(0.f, 0.f, 0.f, 0.f);
    }
    __syncthreads();

    // ---- phase 1: channel mix (scalar). thread (yg = t&7, o = t>>3) ----
    {
        int yg = t & 7, o = t >> 3;
        float4 acc = make_float4(0.f, 0.f, 0.f, 0.f);
        const float4* wp = (const float4*)(w + (size_t)o * 1024 + x * 32 + 4 * yg);
        const float4* ap = (const float4*)(As + 4 * yg);
#pragma unroll 8
        for (int i = 0; i < 32; i++) {
            float4 wv = __ldg(&wp[(size_t)i * 8192]);
            float4 av = ap[i * 9];
            acc.x += av.x * wv.x;
            acc.y += av.y * wv.y;
            acc.z += av.z * wv.z;
            acc.w += av.w * wv.w;
        }
        *(float4*)&rst[o * 36 + 4 * yg] = acc;    // natural [o][y]
    }
    __syncthreads();

    // ---- phase 2: out = R(32o x 32y) @ Mm(32y x 256k) via mma, 3xTF32 ----
    {
        int mt = warp & 1, ntg = warp >> 1;
        int r0 = 16 * mt + g;
        uint32_t Ah[4][4], Al[4][4];
#pragma unroll
        for (int ks = 0; ks < 4; ks++) {
            float f0 = rst[r0 * 36 + 8 * ks + c];
            float f1 = rst[(r0 + 8) * 36 + 8 * ks + c];
            float f2 = rst[r0 * 36 + 8 * ks + c + 4];
            float f3 = rst[(r0 + 8) * 36 + 8 * ks + c + 4];
            Ah[ks][0] = cvt_tf32(f0); Al[ks][0] = __float_as_uint(f0 - __uint_as_float(Ah[ks][0]));
            Ah[ks][1] = cvt_tf32(f1); Al[ks][1] = __float_as_uint(f1 - __uint_as_float(Ah[ks][1]));
            Ah[ks][2] = cvt_tf32(f2); Al[ks][2] = __float_as_uint(f2 - __uint_as_float(Ah[ks][2]));
            Ah[ks][3] = cvt_tf32(f3); Al[ks][3] = __float_as_uint(f3 - __uint_as_float(Ah[ks][3]));
        }
#pragma unroll
        for (int j = 0; j < 8; j++) {
            int nt = ntg * 8 + j;
            float d0 = 0.f, d1 = 0.f, d2 = 0.f, d3 = 0.f;
            const float4* PM = (const float4*)g_T.PM + nt * 32 + lane;
#pragma unroll
            for (int ks = 0; ks < 4; ks++) {
                float4 bf = __ldg(PM + ks * 1024);
                uint32_t b0h = __float_as_uint(bf.x), b1h = __float_as_uint(bf.y);
                uint32_t b0l = __float_as_uint(bf.z), b1l = __float_as_uint(bf.w);
                MMA_TF32(d0, d1, d2, d3, Ah[ks][0], Ah[ks][1], Ah[ks][2], Ah[ks][3], b0h, b1h);
                MMA_TF32(d0, d1, d2, d3, Al[ks][0], Al[ks][1], Al[ks][2], Al[ks][3], b0h, b1h);
                MMA_TF32(d0, d1, d2, d3, Ah[ks][0], Ah[ks][1], Ah[ks][2], Ah[ks][3], b0l, b1l);
            }
            float* op = out + (((size_t)(b * 32 + r0)) * S + row) * S + 8 * nt + 2 * c;
            *(float2*)op = make_float2(d0, d1);
            *(float2*)(op + (size_t)8 * S * S) = make_float2(d2, d3);
        }
    }
}

// ---------------------------------------------------------------------------
extern "C" void kernel_launch(void* const* d_in, const int* in_sizes, int n_in,
                              void* d_out, int out_size) {
    const float* x  = (const float*)d_in[0];
    const float* w1 = (const float*)d_in[1];
    const float* w2 = (const float*)d_in[2];
    float* out = (float*)d_out;

    f_fused<<<NB * 2 * 32, 256>>>(x, w1, w2, out);
}

// round 17
// speedup vs baseline: 1.0625x; 1.0625x over previous
#include <cuda_runtime.h>
#include <cstdint>

// SpectralConv2d via DHT — fused kernel (R15 base: 3-chain 3xTF32 mma).
// R17: phase-1 w loads hoisted — first 8 LDG.128 issued BEFORE barrier 1 so
// they overlap x-load wait + phase A; zero-fill also moved pre-barrier.

#define NB 8
#define S  256

// ---------------------------------------------------------------------------
// Compile-time trig + tf32 fragment tables.
// ---------------------------------------------------------------------------
constexpr double CPI = 3.14159265358979323846264338327950288;

constexpr double tpoly_cos(double x) {
    double x2 = x * x, term = 1.0, sum = 1.0;
    for (int n = 1; n <= 12; n++) { term *= -x2 / ((2.0*n - 1) * (2.0*n)); sum += term; }
    return sum;
}
constexpr double tpoly_sin(double x) {
    double x2 = x * x, term = x, sum = x;
    for (int n = 1; n <= 12; n++) { term *= -x2 / ((2.0*n) * (2.0*n + 1)); sum += term; }
    return sum;
}
constexpr double cos256(int m) {
    m &= 255; int s = 1;
    if (m > 128) m = 256 - m;
    if (m > 64) { m = 128 - m; s = -1; }
    return s * tpoly_cos((CPI * m) / 128.0);
}
constexpr double sin256(int m) {
    m &= 255; int s = 1;
    if (m > 128) { m = 256 - m; s = -1; }
    if (m > 64) { m = 128 - m; }
    return s * tpoly_sin((CPI * m) / 128.0);
}
constexpr double casd(int m) { return cos256(m) + sin256(m); }

constexpr float tf_hi(double v) {
    float f = (float)v;
    unsigned u = __builtin_bit_cast(unsigned, f);
    u &= 0xFFFFE000u;
    return __builtin_bit_cast(float, u);
}
constexpr float tf_lo(double v) {
    float h = tf_hi(v);
    float l = (float)(v - (double)h);
    unsigned u = __builtin_bit_cast(unsigned, l);
    u &= 0xFFFFE000u;
    return __builtin_bit_cast(float, u);
}

struct alignas(16) F4 { float x, y, z, w; };

// PA[(ks*4+nt)*32+lane]: B-frag for phase A  (B is 256k x 32y, K-dim = k)
//   lane: c = lane&3, g = lane>>2; {b0_hi, b1_hi, b0_lo, b1_lo}
// PM[(ks*32+nt)*32+lane]: same packing for Mm (32y x 256k, K-dim = y)
struct Tables {
    F4 PA[32 * 4 * 32];
    F4 PM[4 * 32 * 32];
};

constexpr Tables make_tables() {
    Tables t{};
    double cas[256] = {};
    for (int m = 0; m < 256; m++) cas[m] = casd(m);
    for (int ks = 0; ks < 32; ks++)
        for (int nt = 0; nt < 4; nt++)
            for (int lane = 0; lane < 32; lane++) {
                int c = lane & 3, g = lane >> 2;
                int k0 = 8 * ks + c, k1 = k0 + 4, y = 8 * nt + g;
                double b0 = cas[(k0 * y) & 255], b1 = cas[(k1 * y) & 255];
                t.PA[(ks * 4 + nt) * 32 + lane] =
                    F4{tf_hi(b0), tf_hi(b1), tf_lo(b0), tf_lo(b1)};
            }
    for (int ks = 0; ks < 4; ks++)
        for (int nt = 0; nt < 32; nt++)
            for (int lane = 0; lane < 32; lane++) {
                int c = lane & 3, g = lane >> 2;
                int y0 = 8 * ks + c, y1 = y0 + 4, k = 8 * nt + g;
                double m0 = 0.0, m1 = 0.0;
                for (int j = 0; j < 32; j++) {
                    double cj = cas[(j * k) & 255];
                    m0 += cas[(8 * ((y0 * j) & 31)) & 255] * cj;
                    m1 += cas[(8 * ((y1 * j) & 31)) & 255] * cj;
                }
                m0 *= 0x1p-42; m1 *= 0x1p-42;
                t.PM[(ks * 32 + nt) * 32 + lane] =
                    F4{tf_hi(m0), tf_hi(m1), tf_lo(m0), tf_lo(m1)};
            }
    return t;
}

__device__ const Tables g_T = make_tables();

// ---------------------------------------------------------------------------
__device__ __forceinline__ uint32_t cvt_tf32(float f) {
    uint32_t r; asm("cvt.rna.tf32.f32 %0, %1;" : "=r"(r) : "f"(f)); return r;
}
#define MMA_TF32(d0,d1,d2,d3,a0,a1,a2,a3,b0,b1)                             \
    asm("mma.sync.aligned.m16n8k8.row.col.f32.tf32.tf32.f32 "               \
        "{%0,%1,%2,%3}, {%4,%5,%6,%7}, {%8,%9}, {%0,%1,%2,%3};"             \
        : "+f"(d0), "+f"(d1), "+f"(d2), "+f"(d3)                            \
        : "r"(a0), "r"(a1), "r"(a2), "r"(a3), "r"(b0), "r"(b1))

// ---------------------------------------------------------------------------
// F: fused DHT (mma) + channel mix (scalar) + trailing transforms (mma).
// One block per (b, blk, x); 256 threads = 8 warps.
// ---------------------------------------------------------------------------
__global__ __launch_bounds__(256) void f_fused(const float* __restrict__ xin,
                                               const float* __restrict__ w1,
                                               const float* __restrict__ w2,
                                               float* __restrict__ out) {
    __shared__ float xs[32 * 260];   // [i][k], pitch 260 (frag-LDS conflict-free)
    __shared__ float As[32 * 36];    // [i][y], pitch 36
    __shared__ float rst[32 * 36];   // [o][y], pitch 36

    int t    = threadIdx.x;
    int lane = t & 31, warp = t >> 5;
    int g    = lane >> 2, c = lane & 3;
    int bid  = blockIdx.x;
    int x    = bid & 31;
    int blk  = (bid >> 5) & 1;
    int b    = bid >> 6;
    int row  = blk ? (224 + x) : x;
    const float* w = blk ? w2 : w1;

    // ---- stage x rows into xs (coalesced) ----
    const float4* xb4 = (const float4*)(xin + (((size_t)b * 32) * S + row) * S);
#pragma unroll
    for (int n = t; n < 2048; n += 256) {
        int i = n >> 6, kc = n & 63;
        ((float4*)(xs + i * 260))[kc] = xb4[(size_t)i * (S * S / 4) + kc];
    }

    // ---- hoisted phase-1 w prefetch: 8 LDG.128 in flight across phase A ----
    int yg = t & 7, o = t >> 3;
    const float4* wp = (const float4*)(w + (size_t)o * 1024 + x * 32 + 4 * yg);
    float4 wbuf[8];
#pragma unroll
    for (int q = 0; q < 8; q++) wbuf[q] = __ldg(&wp[(size_t)q * 8192]);

    // ---- zero-fill dead rows [32,224): drains during x-load barrier wait ----
    {
        int img = bid >> 1, half = bid & 1;
        float4* o4 = (float4*)out + (size_t)img * 16384 + 2048 + half * 6144 + t;
#pragma unroll
        for (int j = 0; j < 24; j++) o4[j * 256] = make_float4(0.f, 0.f, 0.f, 0.f);
    }
    __syncthreads();

    // ---- phase A: A = X(32i x 256k) @ B(256k x 32y); 3 independent chains ----
    {
        int mt = warp >> 2, nt = warp & 3;
        const float* xr0 = xs + (16 * mt + g) * 260;
        const float* xr1 = xr0 + 8 * 260;
        float hh0=0.f,hh1=0.f,hh2=0.f,hh3=0.f;   // A_hi * B_hi
        float lh0=0.f,lh1=0.f,lh2=0.f,lh3=0.f;   // A_lo * B_hi
        float hl0=0.f,hl1=0.f,hl2=0.f,hl3=0.f;   // A_hi * B_lo
        const float4* PA = (const float4*)g_T.PA + nt * 32 + lane;
#pragma unroll 8
        for (int ks = 0; ks < 32; ks++) {
            float f0 = xr0[8 * ks + c];
            float f1 = xr1[8 * ks + c];
            float f2 = xr0[8 * ks + c + 4];
            float f3 = xr1[8 * ks + c + 4];
            uint32_t a0h = cvt_tf32(f0), a1h = cvt_tf32(f1);
            uint32_t a2h = cvt_tf32(f2), a3h = cvt_tf32(f3);
            uint32_t a0l = __float_as_uint(f0 - __uint_as_float(a0h));
            uint32_t a1l = __float_as_uint(f1 - __uint_as_float(a1h));
            uint32_t a2l = __float_as_uint(f2 - __uint_as_float(a2h));
            uint32_t a3l = __float_as_uint(f3 - __uint_as_float(a3h));
            float4 bf = __ldg(PA + ks * 128);
            uint32_t b0h = __float_as_uint(bf.x), b1h = __float_as_uint(bf.y);
            uint32_t b0l = __float_as_uint(bf.z), b1l = __float_as_uint(bf.w);
            MMA_TF32(hh0, hh1, hh2, hh3, a0h, a1h, a2h, a3h, b0h, b1h);
            MMA_TF32(lh0, lh1, lh2, lh3, a0l, a1l, a2l, a3l, b0h, b1h);
            MMA_TF32(hl0, hl1, hl2, hl3, a0h, a1h, a2h, a3h, b0l, b1l);
        }
        float d0 = (hh0 + lh0) + hl0;
        float d1 = (hh1 + lh1) + hl1;
        float d2 = (hh2 + lh2) + hl2;
        float d3 = (hh3 + lh3) + hl3;
        int i0 = 16 * mt + g, y0 = 8 * nt + 2 * c;
        *(float2*)&As[i0 * 36 + y0]       = make_float2(d0, d1);
        *(float2*)&As[(i0 + 8) * 36 + y0] = make_float2(d2, d3);
    }
    __syncthreads();

    // ---- phase 1: channel mix; first 8 iterations from the prefetch ----
    {
        float4 acc = make_float4(0.f, 0.f, 0.f, 0.f);
        const float4* ap = (const float4*)(As + 4 * yg);
#pragma unroll
        for (int i = 0; i < 8; i++) {
            float4 wv = wbuf[i];
            float4 av = ap[i * 9];
            acc.x += av.x * wv.x;
            acc.y += av.y * wv.y;
            acc.z += av.z * wv.z;
            acc.w += av.w * wv.w;
        }
#pragma unroll 8
        for (int i = 8; i < 32; i++) {
            float4 wv = __ldg(&wp[(size_t)i * 8192]);
            float4 av = ap[i * 9];
            acc.x += av.x * wv.x;
            acc.y += av.y * wv.y;
            acc.z += av.z * wv.z;
            acc.w += av.w * wv.w;
        }
        *(float4*)&rst[o * 36 + 4 * yg] = acc;    // natural [o][y]
    }
    __syncthreads();

    // ---- phase 2: out = R(32o x 32y) @ Mm(32y x 256k) via mma, 3xTF32 ----
    {
        int mt = warp & 1, ntg = warp >> 1;
        int r0 = 16 * mt + g;
        uint32_t Ah[4][4], Al[4][4];
#pragma unroll
        for (int ks = 0; ks < 4; ks++) {
            float f0 = rst[r0 * 36 + 8 * ks + c];
            float f1 = rst[(r0 + 8) * 36 + 8 * ks + c];
            float f2 = rst[r0 * 36 + 8 * ks + c + 4];
            float f3 = rst[(r0 + 8) * 36 + 8 * ks + c + 4];
            Ah[ks][0] = cvt_tf32(f0); Al[ks][0] = __float_as_uint(f0 - __uint_as_float(Ah[ks][0]));
            Ah[ks][1] = cvt_tf32(f1); Al[ks][1] = __float_as_uint(f1 - __uint_as_float(Ah[ks][1]));
            Ah[ks][2] = cvt_tf32(f2); Al[ks][2] = __float_as_uint(f2 - __uint_as_float(Ah[ks][2]));
            Ah[ks][3] = cvt_tf32(f3); Al[ks][3] = __float_as_uint(f3 - __uint_as_float(Ah[ks][3]));
        }
#pragma unroll
        for (int j = 0; j < 8; j++) {
            int nt = ntg * 8 + j;
            float d0 = 0.f, d1 = 0.f, d2 = 0.f, d3 = 0.f;
            const float4* PM = (const float4*)g_T.PM + nt * 32 + lane;
#pragma unroll
            for (int ks = 0; ks < 4; ks++) {
                float4 bf = __ldg(PM + ks * 1024);
                uint32_t b0h = __float_as_uint(bf.x), b1h = __float_as_uint(bf.y);
                uint32_t b0l = __float_as_uint(bf.z), b1l = __float_as_uint(bf.w);
                MMA_TF32(d0, d1, d2, d3, Ah[ks][0], Ah[ks][1], Ah[ks][2], Ah[ks][3], b0h, b1h);
                MMA_TF32(d0, d1, d2, d3, Al[ks][0], Al[ks][1], Al[ks][2], Al[ks][3], b0h, b1h);
                MMA_TF32(d0, d1, d2, d3, Ah[ks][0], Ah[ks][1], Ah[ks][2], Ah[ks][3], b0l, b1l);
            }
            float* op = out + (((size_t)(b * 32 + r0)) * S + row) * S + 8 * nt + 2 * c;
            *(float2*)op = make_float2(d0, d1);
            *(float2*)(op + (size_t)8 * S * S) = make_float2(d2, d3);
        }
    }
}

// ---------------------------------------------------------------------------
extern "C" void kernel_launch(void* const* d_in, const int* in_sizes, int n_in,
                              void* d_out, int out_size) {
    const float* x  = (const float*)d_in[0];
    const float* w1 = (const float*)d_in[1];
    const float* w2 = (const float*)d_in[2];
    float* out = (float*)d_out;

    f_fused<<<NB * 2 * 32, 256>>>(x, w1, w2, out);
}